// round 5
// baseline (speedup 1.0000x reference)
#include <cuda_runtime.h>
#include <cuda_fp16.h>
#include <cstdint>
#include <math.h>

#define BATCH 64
#define ONUM  32
#define INUM  512
#define DD    64
#define OD    2048               // ONUM*DD

// ---------------- scratch (device globals) -----------------------------------
__device__ __half g_xhat[(size_t)BATCH * INUM * OD];   // [b][i][o][d] fp16, 134MB
__device__ float g_s[3][BATCH * OD];
__device__ float g_out0[BATCH * OD];
__device__ float g_out1[BATCH * OD];
__device__ float g_b1[(size_t)BATCH * INUM * ONUM];

// ---------------- helpers -----------------------------------------------------
__device__ __forceinline__ uint32_t smem_u32(const void* p) {
    uint32_t a;
    asm("{ .reg .u64 t; cvta.to.shared.u64 t, %1; cvt.u32.u64 %0, t; }" : "=r"(a) : "l"(p));
    return a;
}
__device__ __forceinline__ uint2 f4_to_h4(float4 v) {
    __half2 h0 = __floats2half2_rn(v.x, v.y);
    __half2 h1 = __floats2half2_rn(v.z, v.w);
    return make_uint2(*(uint32_t*)&h0, *(uint32_t*)&h1);
}
__device__ __forceinline__ uint32_t f2_to_h2(float a, float b) {
    __half2 h = __floats2half2_rn(a, b);
    return *(uint32_t*)&h;
}
__device__ __forceinline__ void ldmx4(uint32_t* r, uint32_t addr) {
    asm volatile("ldmatrix.sync.aligned.m8n8.x4.shared.b16 {%0,%1,%2,%3}, [%4];"
                 : "=r"(r[0]), "=r"(r[1]), "=r"(r[2]), "=r"(r[3]) : "r"(addr));
}
__device__ __forceinline__ void mma16816(float* c, const uint32_t* a, uint32_t b0, uint32_t b1) {
    asm volatile("mma.sync.aligned.m16n8k16.row.col.f32.f16.f16.f32 "
                 "{%0,%1,%2,%3}, {%4,%5,%6,%7}, {%8,%9}, {%0,%1,%2,%3};"
                 : "+f"(c[0]), "+f"(c[1]), "+f"(c[2]), "+f"(c[3])
                 : "r"(a[0]), "r"(a[1]), "r"(a[2]), "r"(a[3]), "r"(b0), "r"(b1));
}

// ---------------- zero --------------------------------------------------------
__global__ void zero_s_kernel() {
    int idx = blockIdx.x * blockDim.x + threadIdx.x;
    if (idx < 3 * BATCH * OD) (&g_s[0][0])[idx] = 0.0f;
}

// ---------------- HMMA GEMM: x_hat + fused s0 (unchanged, at DRAM roofline) ---
#define WT_S 72
#define XT_S 72
#define OT_S 136

__global__ __launch_bounds__(256, 2) void gemm_xhat_hmma(
    const float* __restrict__ x, const float* __restrict__ w)
{
    __shared__ __align__(16) __half Wt[128 * WT_S];  // [od][m]
    __shared__ __align__(16) __half Xt[64 * XT_S];   // [b][m]
    __shared__ __align__(16) __half Ot[64 * OT_S];   // [b][od 0..127]

    const int tid = threadIdx.x, wid = tid >> 5, lane = tid & 31;
    const int p = blockIdx.x;
    const int ibase = blockIdx.y * 16;

    const uint32_t wbase = smem_u32(Wt);
    const uint32_t xbase = smem_u32(Xt);

    const float4* wf4 = (const float4*)w;
    const float4* xf4 = (const float4*)x;

    const int wm = wid & 1;
    const int wn = wid >> 1;
    const int r0a = wm * 32;
    const int n0  = wn * 32;

    const int a_row_off = (lane & 7) + ((lane >> 3) & 1) * 8;
    const int a_col_off = (lane >= 16) ? 8 : 0;
    const int b_row_off = (lane & 7) + ((lane >> 4) & 1) * 8;
    const int b_col_off = ((lane >> 3) & 1) * 8;

    float s0acc[4][8];
#pragma unroll
    for (int j = 0; j < 4; j++)
#pragma unroll
        for (int e = 0; e < 8; e++) s0acc[j][e] = 0.0f;

    for (int t = 0; t < 16; t++) {
        const int i = ibase + t;

#pragma unroll
        for (int k = 0; k < 8; k++) {
            int g = tid + k * 256;
            int ol = g >> 10, rem = g & 1023;
            float4 v = wf4[(((size_t)(2 * p + ol) * INUM + i) << 10) + rem];
            *(uint2*)&Wt[(ol * 64 + (rem >> 4)) * WT_S + (rem & 15) * 4] = f4_to_h4(v);
        }
#pragma unroll
        for (int j = 0; j < 4; j++) {
            int idx = tid + j * 256;
            int b = idx >> 4, mq = idx & 15;
            float4 v = xf4[((size_t)b * INUM + i) * 16 + mq];
            *(uint2*)&Xt[b * XT_S + mq * 4] = f4_to_h4(v);
        }
        __syncthreads();

        float acc[2][4][4];
#pragma unroll
        for (int mt = 0; mt < 2; mt++)
#pragma unroll
            for (int nt = 0; nt < 4; nt++)
#pragma unroll
                for (int e = 0; e < 4; e++) acc[mt][nt][e] = 0.0f;

#pragma unroll
        for (int ks = 0; ks < 4; ks++) {
            const int kc = ks * 16;
            uint32_t afr[2][4], bfr[2][4];
#pragma unroll
            for (int mt = 0; mt < 2; mt++) {
                int row = r0a + mt * 16 + a_row_off;
                int col = kc + a_col_off;
                ldmx4(afr[mt], xbase + (row * XT_S + col) * 2);
            }
#pragma unroll
            for (int nt2 = 0; nt2 < 2; nt2++) {
                int row = n0 + nt2 * 16 + b_row_off;
                int col = kc + b_col_off;
                ldmx4(bfr[nt2], wbase + (row * WT_S + col) * 2);
            }
#pragma unroll
            for (int mt = 0; mt < 2; mt++) {
#pragma unroll
                for (int nt = 0; nt < 4; nt++) {
                    uint32_t b0 = bfr[nt >> 1][(nt & 1) * 2 + 0];
                    uint32_t b1 = bfr[nt >> 1][(nt & 1) * 2 + 1];
                    mma16816(acc[mt][nt], afr[mt], b0, b1);
                }
            }
        }

#pragma unroll
        for (int mt = 0; mt < 2; mt++) {
            int row = r0a + mt * 16 + (lane >> 2);
#pragma unroll
            for (int nt = 0; nt < 4; nt++) {
                int col = n0 + nt * 8 + (lane & 3) * 2;
                *(uint32_t*)&Ot[row * OT_S + col] = f2_to_h2(acc[mt][nt][0], acc[mt][nt][1]);
                *(uint32_t*)&Ot[(row + 8) * OT_S + col] = f2_to_h2(acc[mt][nt][2], acc[mt][nt][3]);
            }
        }
        __syncthreads();

#pragma unroll
        for (int j = 0; j < 4; j++) {
            int idx = tid + j * 256;
            int brow = idx >> 4, chunk = idx & 15;
            uint4 v = *(const uint4*)&Ot[brow * OT_S + chunk * 8];
            const __half2* h = (const __half2*)&v;
#pragma unroll
            for (int q = 0; q < 4; q++) {
                float2 f = __half22float2(h[q]);
                s0acc[j][q * 2 + 0] += f.x;
                s0acc[j][q * 2 + 1] += f.y;
            }
            *(uint4*)&g_xhat[((size_t)brow * INUM + i) * OD + p * 128 + chunk * 8] = v;
        }
        __syncthreads();
    }

    const float sc = 1.0f / (float)ONUM;
#pragma unroll
    for (int j = 0; j < 4; j++) {
        int idx = tid + j * 256;
        int brow = idx >> 4, chunk = idx & 15;
        float* sp = &g_s[0][brow * OD + p * 128 + chunk * 8];
#pragma unroll
        for (int e = 0; e < 8; e++)
            atomicAdd(sp + e, s0acc[j][e] * sc);
    }
}

// ---------------- squash ------------------------------------------------------
__global__ void squash_kernel(const float* __restrict__ s, float* __restrict__ v)
{
    int gw   = (blockIdx.x * blockDim.x + threadIdx.x) >> 5;
    int lane = threadIdx.x & 31;
    if (gw >= BATCH * ONUM) return;
    const float* row = s + (size_t)gw * 64;
    float a = row[lane];
    float b = row[lane + 32];
    float ss = a * a + b * b;
#pragma unroll
    for (int off = 16; off; off >>= 1) ss += __shfl_xor_sync(0xffffffffu, ss, off);
    float n = sqrtf(ss);
    float f = (ss / (1.0f + ss)) / (n + 1e-8f);
    v[(size_t)gw * 64 + lane]      = a * f;
    v[(size_t)gw * 64 + lane + 32] = b * f;
}

// ---------------- routing pass v3: smem out_prev, high occupancy --------------
// grid (64, 8), block 128 (4 warps). warp -> (b, 16 i's); lane = o.
// ops: stride 68 (conflict-free LDS.128); red: stride 65 (conflict-free atoms).
#define OPS_S 68
#define RED_S 65
template <int MODE>
__global__ __launch_bounds__(128, 3) void route_v3(
    const float* __restrict__ out_prev, float* __restrict__ s_next)
{
    __shared__ __align__(16) float ops[ONUM * OPS_S];
    __shared__ float red[ONUM * RED_S];

    const int tid = threadIdx.x, wid = tid >> 5, lane = tid & 31;
    const int b = blockIdx.x;
    const int i0 = (blockIdx.y * 4 + wid) * 16;

    // cooperative load of out_prev[b] into ops[o][d]
    {
        const float4* src = (const float4*)(out_prev + (size_t)b * OD);
        for (int c = tid; c < 512; c += 128) {
            int o = c >> 4, q = c & 15;
            *(float4*)&ops[o * OPS_S + q * 4] = src[c];
        }
        for (int k = tid; k < ONUM * RED_S; k += 128) red[k] = 0.0f;
    }
    __syncthreads();

    float sacc[64];
#pragma unroll
    for (int d = 0; d < 64; d++) sacc[d] = 0.0f;

    const uint4* xp = (const uint4*)(g_xhat + (size_t)b * INUM * OD + (size_t)i0 * OD + lane * 64);
    float* b1p = g_b1 + ((size_t)b * INUM + i0) * ONUM + lane;
    const float* opr = &ops[lane * OPS_S];

    uint4 cur[8], nxt[8];
#pragma unroll
    for (int c = 0; c < 8; c++) cur[c] = xp[c];

    for (int ii = 0; ii < 16; ii++) {
        if (ii + 1 < 16) {
            const uint4* np = xp + (size_t)(ii + 1) * (OD / 8);
#pragma unroll
            for (int c = 0; c < 8; c++) nxt[c] = np[c];
        }

        // agreement dot (out_prev from conflict-free smem)
        float pdot = 0.0f;
#pragma unroll
        for (int c = 0; c < 8; c++) {
            const __half2* h = (const __half2*)&cur[c];
            float4 oa = *(const float4*)&opr[c * 8];
            float4 ob = *(const float4*)&opr[c * 8 + 4];
            float2 f0 = __half22float2(h[0]);
            float2 f1 = __half22float2(h[1]);
            float2 f2 = __half22float2(h[2]);
            float2 f3 = __half22float2(h[3]);
            pdot += f0.x * oa.x + f0.y * oa.y + f1.x * oa.z + f1.y * oa.w
                  + f2.x * ob.x + f2.y * ob.y + f3.x * ob.z + f3.y * ob.w;
        }
        if (MODE == 1) pdot += b1p[ii * ONUM];
        else           b1p[ii * ONUM] = pdot;

        // softmax over 32 o's (pure warp shuffles)
        float m = pdot;
#pragma unroll
        for (int off = 16; off; off >>= 1)
            m = fmaxf(m, __shfl_xor_sync(0xffffffffu, m, off));
        float e = __expf(pdot - m);
        float ssum = e;
#pragma unroll
        for (int off = 16; off; off >>= 1)
            ssum += __shfl_xor_sync(0xffffffffu, ssum, off);
        float c = e / ssum;

        // weighted accumulate
#pragma unroll
        for (int cc = 0; cc < 8; cc++) {
            const __half2* h = (const __half2*)&cur[cc];
            float2 f0 = __half22float2(h[0]);
            float2 f1 = __half22float2(h[1]);
            float2 f2 = __half22float2(h[2]);
            float2 f3 = __half22float2(h[3]);
            sacc[cc * 8 + 0] += c * f0.x; sacc[cc * 8 + 1] += c * f0.y;
            sacc[cc * 8 + 2] += c * f1.x; sacc[cc * 8 + 3] += c * f1.y;
            sacc[cc * 8 + 4] += c * f2.x; sacc[cc * 8 + 5] += c * f2.y;
            sacc[cc * 8 + 6] += c * f3.x; sacc[cc * 8 + 7] += c * f3.y;
        }
#pragma unroll
        for (int c2 = 0; c2 < 8; c2++) cur[c2] = nxt[c2];
    }

    // CTA reduction (stride-65: bank = (o+d) mod 32, conflict-free)
#pragma unroll
    for (int d = 0; d < 64; d++)
        atomicAdd(&red[lane * RED_S + d], sacc[d]);
    __syncthreads();

    // coalesced global atomics
    for (int k = tid; k < OD; k += 128) {
        int o = k >> 6, d = k & 63;
        atomicAdd(&s_next[(size_t)b * OD + k], red[o * RED_S + d]);
    }
}

// ---------------- launch ------------------------------------------------------
extern "C" void kernel_launch(void* const* d_in, const int* in_sizes, int n_in,
                              void* d_out, int out_size)
{
    const float* x = (const float*)d_in[0];
    const float* w = (const float*)d_in[1];
    float* out = (float*)d_out;

    float* s_base;  cudaGetSymbolAddress((void**)&s_base,  g_s);
    float* out0;    cudaGetSymbolAddress((void**)&out0,    g_out0);
    float* out1;    cudaGetSymbolAddress((void**)&out1,    g_out1);
    float* s0 = s_base;
    float* s1 = s_base + BATCH * OD;
    float* s2 = s_base + 2 * BATCH * OD;

    zero_s_kernel<<<(3 * BATCH * OD + 255) / 256, 256>>>();

    gemm_xhat_hmma<<<dim3(16, 32), 256>>>(x, w);

    squash_kernel<<<(BATCH * ONUM) / 8, 256>>>(s0, out0);

    route_v3<0><<<dim3(BATCH, 8), 128>>>(out0, s1);

    squash_kernel<<<(BATCH * ONUM) / 8, 256>>>(s1, out1);

    route_v3<1><<<dim3(BATCH, 8), 128>>>(out1, s2);

    squash_kernel<<<(BATCH * ONUM) / 8, 256>>>(s2, out);
}

// round 6
// speedup vs baseline: 1.5271x; 1.5271x over previous
#include <cuda_runtime.h>
#include <cuda_fp16.h>
#include <cstdint>
#include <math.h>

#define BATCH 64
#define ONUM  32
#define INUM  512
#define DD    64
#define OD    2048               // ONUM*DD

// ---------------- scratch (device globals) -----------------------------------
__device__ __half g_xhat[(size_t)BATCH * INUM * OD];   // [b][i][o][d] fp16, 134MB
__device__ float g_s[3][BATCH * OD];
__device__ float g_out0[BATCH * OD];
__device__ float g_out1[BATCH * OD];
__device__ float g_b1[(size_t)BATCH * INUM * ONUM];

// ---------------- helpers -----------------------------------------------------
__device__ __forceinline__ uint32_t smem_u32(const void* p) {
    uint32_t a;
    asm("{ .reg .u64 t; cvta.to.shared.u64 t, %1; cvt.u32.u64 %0, t; }" : "=r"(a) : "l"(p));
    return a;
}
__device__ __forceinline__ uint2 f4_to_h4(float4 v) {
    __half2 h0 = __floats2half2_rn(v.x, v.y);
    __half2 h1 = __floats2half2_rn(v.z, v.w);
    return make_uint2(*(uint32_t*)&h0, *(uint32_t*)&h1);
}
__device__ __forceinline__ uint32_t f2_to_h2(float a, float b) {
    __half2 h = __floats2half2_rn(a, b);
    return *(uint32_t*)&h;
}
__device__ __forceinline__ void ldmx4(uint32_t* r, uint32_t addr) {
    asm volatile("ldmatrix.sync.aligned.m8n8.x4.shared.b16 {%0,%1,%2,%3}, [%4];"
                 : "=r"(r[0]), "=r"(r[1]), "=r"(r[2]), "=r"(r[3]) : "r"(addr));
}
__device__ __forceinline__ void mma16816(float* c, const uint32_t* a, uint32_t b0, uint32_t b1) {
    asm volatile("mma.sync.aligned.m16n8k16.row.col.f32.f16.f16.f32 "
                 "{%0,%1,%2,%3}, {%4,%5,%6,%7}, {%8,%9}, {%0,%1,%2,%3};"
                 : "+f"(c[0]), "+f"(c[1]), "+f"(c[2]), "+f"(c[3])
                 : "r"(a[0]), "r"(a[1]), "r"(a[2]), "r"(a[3]), "r"(b0), "r"(b1));
}
__device__ __forceinline__ void cp16(uint32_t dst, const void* src) {
    asm volatile("cp.async.cg.shared.global [%0], [%1], 16;" :: "r"(dst), "l"(src));
}
#define CP_COMMIT() asm volatile("cp.async.commit_group;" ::: "memory")

// ---------------- zero --------------------------------------------------------
__global__ void zero_s_kernel() {
    int idx = blockIdx.x * blockDim.x + threadIdx.x;
    if (idx < 3 * BATCH * OD) (&g_s[0][0])[idx] = 0.0f;
}

// ---------------- HMMA GEMM: x_hat + fused s0 (unchanged, at DRAM roofline) ---
#define WT_S 72
#define XT_S 72
#define OT_S 136

__global__ __launch_bounds__(256, 2) void gemm_xhat_hmma(
    const float* __restrict__ x, const float* __restrict__ w)
{
    __shared__ __align__(16) __half Wt[128 * WT_S];  // [od][m]
    __shared__ __align__(16) __half Xt[64 * XT_S];   // [b][m]
    __shared__ __align__(16) __half Ot[64 * OT_S];   // [b][od 0..127]

    const int tid = threadIdx.x, wid = tid >> 5, lane = tid & 31;
    const int p = blockIdx.x;
    const int ibase = blockIdx.y * 16;

    const uint32_t wbase = smem_u32(Wt);
    const uint32_t xbase = smem_u32(Xt);

    const float4* wf4 = (const float4*)w;
    const float4* xf4 = (const float4*)x;

    const int wm = wid & 1;
    const int wn = wid >> 1;
    const int r0a = wm * 32;
    const int n0  = wn * 32;

    const int a_row_off = (lane & 7) + ((lane >> 3) & 1) * 8;
    const int a_col_off = (lane >= 16) ? 8 : 0;
    const int b_row_off = (lane & 7) + ((lane >> 4) & 1) * 8;
    const int b_col_off = ((lane >> 3) & 1) * 8;

    float s0acc[4][8];
#pragma unroll
    for (int j = 0; j < 4; j++)
#pragma unroll
        for (int e = 0; e < 8; e++) s0acc[j][e] = 0.0f;

    for (int t = 0; t < 16; t++) {
        const int i = ibase + t;

#pragma unroll
        for (int k = 0; k < 8; k++) {
            int g = tid + k * 256;
            int ol = g >> 10, rem = g & 1023;
            float4 v = wf4[(((size_t)(2 * p + ol) * INUM + i) << 10) + rem];
            *(uint2*)&Wt[(ol * 64 + (rem >> 4)) * WT_S + (rem & 15) * 4] = f4_to_h4(v);
        }
#pragma unroll
        for (int j = 0; j < 4; j++) {
            int idx = tid + j * 256;
            int b = idx >> 4, mq = idx & 15;
            float4 v = xf4[((size_t)b * INUM + i) * 16 + mq];
            *(uint2*)&Xt[b * XT_S + mq * 4] = f4_to_h4(v);
        }
        __syncthreads();

        float acc[2][4][4];
#pragma unroll
        for (int mt = 0; mt < 2; mt++)
#pragma unroll
            for (int nt = 0; nt < 4; nt++)
#pragma unroll
                for (int e = 0; e < 4; e++) acc[mt][nt][e] = 0.0f;

#pragma unroll
        for (int ks = 0; ks < 4; ks++) {
            const int kc = ks * 16;
            uint32_t afr[2][4], bfr[2][4];
#pragma unroll
            for (int mt = 0; mt < 2; mt++) {
                int row = r0a + mt * 16 + a_row_off;
                int col = kc + a_col_off;
                ldmx4(afr[mt], xbase + (row * XT_S + col) * 2);
            }
#pragma unroll
            for (int nt2 = 0; nt2 < 2; nt2++) {
                int row = n0 + nt2 * 16 + b_row_off;
                int col = kc + b_col_off;
                ldmx4(bfr[nt2], wbase + (row * WT_S + col) * 2);
            }
#pragma unroll
            for (int mt = 0; mt < 2; mt++) {
#pragma unroll
                for (int nt = 0; nt < 4; nt++) {
                    uint32_t b0 = bfr[nt >> 1][(nt & 1) * 2 + 0];
                    uint32_t b1 = bfr[nt >> 1][(nt & 1) * 2 + 1];
                    mma16816(acc[mt][nt], afr[mt], b0, b1);
                }
            }
        }

#pragma unroll
        for (int mt = 0; mt < 2; mt++) {
            int row = r0a + mt * 16 + (lane >> 2);
#pragma unroll
            for (int nt = 0; nt < 4; nt++) {
                int col = n0 + nt * 8 + (lane & 3) * 2;
                *(uint32_t*)&Ot[row * OT_S + col] = f2_to_h2(acc[mt][nt][0], acc[mt][nt][1]);
                *(uint32_t*)&Ot[(row + 8) * OT_S + col] = f2_to_h2(acc[mt][nt][2], acc[mt][nt][3]);
            }
        }
        __syncthreads();

#pragma unroll
        for (int j = 0; j < 4; j++) {
            int idx = tid + j * 256;
            int brow = idx >> 4, chunk = idx & 15;
            uint4 v = *(const uint4*)&Ot[brow * OT_S + chunk * 8];
            const __half2* h = (const __half2*)&v;
#pragma unroll
            for (int q = 0; q < 4; q++) {
                float2 f = __half22float2(h[q]);
                s0acc[j][q * 2 + 0] += f.x;
                s0acc[j][q * 2 + 1] += f.y;
            }
            *(uint4*)&g_xhat[((size_t)brow * INUM + i) * OD + p * 128 + chunk * 8] = v;
        }
        __syncthreads();
    }

    const float sc = 1.0f / (float)ONUM;
#pragma unroll
    for (int j = 0; j < 4; j++) {
        int idx = tid + j * 256;
        int brow = idx >> 4, chunk = idx & 15;
        float* sp = &g_s[0][brow * OD + p * 128 + chunk * 8];
#pragma unroll
        for (int e = 0; e < 8; e++)
            atomicAdd(sp + e, s0acc[j][e] * sc);
    }
}

// ---------------- squash ------------------------------------------------------
__global__ void squash_kernel(const float* __restrict__ s, float* __restrict__ v)
{
    int gw   = (blockIdx.x * blockDim.x + threadIdx.x) >> 5;
    int lane = threadIdx.x & 31;
    if (gw >= BATCH * ONUM) return;
    const float* row = s + (size_t)gw * 64;
    float a = row[lane];
    float b = row[lane + 32];
    float ss = a * a + b * b;
#pragma unroll
    for (int off = 16; off; off >>= 1) ss += __shfl_xor_sync(0xffffffffu, ss, off);
    float n = sqrtf(ss);
    float f = (ss / (1.0f + ss)) / (n + 1e-8f);
    v[(size_t)gw * 64 + lane]      = a * f;
    v[(size_t)gw * 64 + lane + 32] = b * f;
}

// ---------------- routing pass v4: cp.async pipelined stream ------------------
// grid (64, 4), block 128 (4 warps). warp -> (b, 32 i's); lane = o.
// Per-warp 4-stage ring in smem; lane l copies AND reads only row l
// (no intra-warp sync needed). Row stride 144B: LDS.128 conflict-free.
#define STAGES 4
#define TROW   72                      // halves per row (144B)
#define TILE_H (32 * TROW)             // halves per tile (4608B)
#define TILES_BYTES (4 * STAGES * TILE_H * 2)   // 73728
#define RED_S  65
#define ROUTE_SMEM (TILES_BYTES + ONUM * RED_S * 4)

template <int MODE>
__global__ __launch_bounds__(128) void route_v4(
    const float* __restrict__ out_prev, float* __restrict__ s_next)
{
    extern __shared__ __align__(16) char dsm[];
    __half* tiles = (__half*)dsm;
    float*  red   = (float*)(dsm + TILES_BYTES);

    const int tid = threadIdx.x, wid = tid >> 5, lane = tid & 31;
    const int b = blockIdx.x;
    const int i0 = (blockIdx.y * 4 + wid) * 32;

    for (int k = tid; k < ONUM * RED_S; k += 128) red[k] = 0.0f;

    // out_prev[b][o=lane][:] in registers
    float opv[64];
    {
        const float4* opf = (const float4*)(out_prev + (size_t)b * OD + lane * 64);
#pragma unroll
        for (int c = 0; c < 16; c++) {
            float4 v = opf[c];
            opv[c * 4 + 0] = v.x; opv[c * 4 + 1] = v.y;
            opv[c * 4 + 2] = v.z; opv[c * 4 + 3] = v.w;
        }
    }
    __syncthreads();   // red zeroed

    float sacc[64];
#pragma unroll
    for (int d = 0; d < 64; d++) sacc[d] = 0.0f;

    // this lane's stream: 128B row per i
    const __half* gsrc = g_xhat + ((size_t)b * INUM + i0) * OD + lane * 64;
    float* b1p = g_b1 + ((size_t)b * INUM + i0) * ONUM + lane;

    // smem addresses for this lane's row in each stage
    const uint32_t rowbase = smem_u32(tiles) + (wid * STAGES * TILE_H + lane * TROW) * 2;
    __half* rowptr = tiles + wid * STAGES * TILE_H + lane * TROW;

    // prologue: issue 3 tiles
#pragma unroll
    for (int t = 0; t < 3; t++) {
        uint32_t dst = rowbase + t * (TILE_H * 2);
        const char* src = (const char*)(gsrc + (size_t)t * OD);
#pragma unroll
        for (int k = 0; k < 8; k++) cp16(dst + k * 16, src + k * 16);
        CP_COMMIT();
    }

    for (int ii = 0; ii < 32; ii++) {
        if (ii < 30)       asm volatile("cp.async.wait_group 2;" ::: "memory");
        else if (ii == 30) asm volatile("cp.async.wait_group 1;" ::: "memory");
        else               asm volatile("cp.async.wait_group 0;" ::: "memory");

        const __half* row = rowptr + (ii & 3) * TILE_H;

        // agreement dot
        float pdot = 0.0f;
        uint4 hv[8];
#pragma unroll
        for (int c = 0; c < 8; c++) hv[c] = ((const uint4*)row)[c];
#pragma unroll
        for (int c = 0; c < 8; c++) {
            const __half2* h = (const __half2*)&hv[c];
            float2 f0 = __half22float2(h[0]);
            float2 f1 = __half22float2(h[1]);
            float2 f2 = __half22float2(h[2]);
            float2 f3 = __half22float2(h[3]);
            pdot += f0.x * opv[c * 8 + 0] + f0.y * opv[c * 8 + 1]
                  + f1.x * opv[c * 8 + 2] + f1.y * opv[c * 8 + 3]
                  + f2.x * opv[c * 8 + 4] + f2.y * opv[c * 8 + 5]
                  + f3.x * opv[c * 8 + 6] + f3.y * opv[c * 8 + 7];
        }
        if (MODE == 1) pdot += b1p[ii * ONUM];
        else           b1p[ii * ONUM] = pdot;

        // softmax over 32 o's (pure warp shuffles)
        float m = pdot;
#pragma unroll
        for (int off = 16; off; off >>= 1)
            m = fmaxf(m, __shfl_xor_sync(0xffffffffu, m, off));
        float e = __expf(pdot - m);
        float ssum = e;
#pragma unroll
        for (int off = 16; off; off >>= 1)
            ssum += __shfl_xor_sync(0xffffffffu, ssum, off);
        float c = e / ssum;

        // weighted accumulate
#pragma unroll
        for (int cc = 0; cc < 8; cc++) {
            const __half2* h = (const __half2*)&hv[cc];
            float2 f0 = __half22float2(h[0]);
            float2 f1 = __half22float2(h[1]);
            float2 f2 = __half22float2(h[2]);
            float2 f3 = __half22float2(h[3]);
            sacc[cc * 8 + 0] += c * f0.x; sacc[cc * 8 + 1] += c * f0.y;
            sacc[cc * 8 + 2] += c * f1.x; sacc[cc * 8 + 3] += c * f1.y;
            sacc[cc * 8 + 4] += c * f2.x; sacc[cc * 8 + 5] += c * f2.y;
            sacc[cc * 8 + 6] += c * f3.x; sacc[cc * 8 + 7] += c * f3.y;
        }

        // issue tile ii+3
        if (ii + 3 < 32) {
            uint32_t dst = rowbase + ((ii + 3) & 3) * (TILE_H * 2);
            const char* src = (const char*)(gsrc + (size_t)(ii + 3) * OD);
#pragma unroll
            for (int k = 0; k < 8; k++) cp16(dst + k * 16, src + k * 16);
            CP_COMMIT();
        }
    }

    // CTA reduction (stride-65: bank = (o+d) mod 32, conflict-free)
#pragma unroll
    for (int d = 0; d < 64; d++)
        atomicAdd(&red[lane * RED_S + d], sacc[d]);
    __syncthreads();

    for (int k = tid; k < OD; k += 128) {
        int o = k >> 6, d = k & 63;
        atomicAdd(&s_next[(size_t)b * OD + k], red[o * RED_S + d]);
    }
}

// ---------------- launch ------------------------------------------------------
extern "C" void kernel_launch(void* const* d_in, const int* in_sizes, int n_in,
                              void* d_out, int out_size)
{
    const float* x = (const float*)d_in[0];
    const float* w = (const float*)d_in[1];
    float* out = (float*)d_out;

    float* s_base;  cudaGetSymbolAddress((void**)&s_base,  g_s);
    float* out0;    cudaGetSymbolAddress((void**)&out0,    g_out0);
    float* out1;    cudaGetSymbolAddress((void**)&out1,    g_out1);
    float* s0 = s_base;
    float* s1 = s_base + BATCH * OD;
    float* s2 = s_base + 2 * BATCH * OD;

    cudaFuncSetAttribute(route_v4<0>, cudaFuncAttributeMaxDynamicSharedMemorySize, ROUTE_SMEM);
    cudaFuncSetAttribute(route_v4<1>, cudaFuncAttributeMaxDynamicSharedMemorySize, ROUTE_SMEM);

    zero_s_kernel<<<(3 * BATCH * OD + 255) / 256, 256>>>();

    gemm_xhat_hmma<<<dim3(16, 32), 256>>>(x, w);

    squash_kernel<<<(BATCH * ONUM) / 8, 256>>>(s0, out0);

    route_v4<0><<<dim3(BATCH, 4), 128, ROUTE_SMEM>>>(out0, s1);

    squash_kernel<<<(BATCH * ONUM) / 8, 256>>>(s1, out1);

    route_v4<1><<<dim3(BATCH, 4), 128, ROUTE_SMEM>>>(out1, s2);

    squash_kernel<<<(BATCH * ONUM) / 8, 256>>>(s2, out);
}